// round 14
// baseline (speedup 1.0000x reference)
#include <cuda_runtime.h>
#include <cuda_fp16.h>
#include <math.h>

// ---------------- problem constants ----------------
#define NB 2
#define NV 3
#define NC 32
#define ND 48
#define NH 128
#define NW 160
#define NHW (NH*NW)          // 20480

typedef unsigned long long ull;

// ---------------- device scratch ----------------
// Feature layout: (V, B, cg=8, H, W, 4ch) fp32, pixel stride 16B
__device__ __align__(128) float g_featT[(size_t)NV*NB*NHW*NC];
// Variance volume fp16: (B, cg=8, D, H, W) x 4ch packed in uint2 (2x half2)
__device__ __align__(128) uint2 g_varH[(size_t)NB*8*ND*NHW];
__device__ __align__(16) float g_cost[(size_t)NB*ND*NHW];
__device__ float g_rot[NB][2][9];
__device__ float g_trans[NB][2][3];
// conv weights as float2 per (cg,chp,kh,kw,kd): [(cg*2+chp)*27 + (kh*3+kw)*3 + kd]
__device__ __align__(16) float g_wcf[864];
__device__ float g_bias;

// ---------------- packed f32x2 helpers ----------------
__device__ __forceinline__ ull fma2(ull a, ull b, ull c) {
    ull d; asm("fma.rn.f32x2 %0, %1, %2, %3;" : "=l"(d) : "l"(a), "l"(b), "l"(c)); return d;
}
__device__ __forceinline__ ull mul2(ull a, ull b) {
    ull d; asm("mul.rn.f32x2 %0, %1, %2;" : "=l"(d) : "l"(a), "l"(b)); return d;
}
__device__ __forceinline__ ull add2(ull a, ull b) {
    ull d; asm("add.rn.f32x2 %0, %1, %2;" : "=l"(d) : "l"(a), "l"(b)); return d;
}
__device__ __forceinline__ ull dup2(float f) {
    ull d; int r = __float_as_int(f);
    asm("mov.b64 %0, {%1, %1};" : "=l"(d) : "r"(r)); return d;
}
__device__ __forceinline__ float sum2(ull v) {
    int lo, hi; asm("mov.b64 {%0, %1}, %2;" : "=r"(lo), "=r"(hi) : "l"(v));
    return __int_as_float(lo) + __int_as_float(hi);
}
// f32x2 (ull) -> half2 bits
__device__ __forceinline__ unsigned pkh2(ull v) {
    float lo, hi;
    asm("mov.b64 {%0, %1}, %2;" : "=f"(lo), "=f"(hi) : "l"(v));
    unsigned r;
    asm("cvt.rn.f16x2.f32 %0, %1, %2;" : "=r"(r) : "f"(hi), "f"(lo));
    return r;
}
// half2 bits -> f32x2 (ull)
__device__ __forceinline__ ull h2f2(unsigned h) {
    float lo, hi;
    asm("{ .reg .f16 l, u; mov.b32 {l, u}, %2; cvt.f32.f16 %0, l; cvt.f32.f16 %1, u; }"
        : "=f"(lo), "=f"(hi) : "r"(h));
    ull d; asm("mov.b64 %0, {%1, %2};" : "=l"(d) : "f"(lo), "f"(hi));
    return d;
}
#define NEGMASK 0x8000000080000000ULL
#define INV3P   0x3eaaaaab3eaaaaabULL   // (1/3, 1/3)

// ---------------- prep: proj @ inv(ref_proj), weight relayout ----------------
__global__ void prep_kernel(const float* __restrict__ proj,
                            const float* __restrict__ rw,
                            const float* __restrict__ rb) {
    int tid = threadIdx.x;
    // rw layout (1,C,3,3,3): rw[c*27 + kd*9 + kh*3 + kw], c = cg*4 + chp*2 + lane
    for (int i = tid; i < 27*NC; i += blockDim.x) {
        int c = i / 27, k = i - c*27;
        int kd = k / 9, kh = (k - kd*9) / 3, kw = k % 3;
        int cg = c >> 2, chp = (c >> 1) & 1, lane = c & 1;
        g_wcf[(((cg*2 + chp)*27) + (kh*3 + kw)*3 + kd)*2 + lane] = rw[i];
    }
    if (tid == 0) g_bias = rb[0];
    if (tid < NB) {
        int b = tid;
        const float* refp = proj + ((size_t)b*NV + 0)*16;
        double a[4][8];
        for (int r = 0; r < 4; r++)
            for (int c2 = 0; c2 < 4; c2++) {
                a[r][c2] = (double)refp[r*4+c2];
                a[r][4+c2] = (r == c2) ? 1.0 : 0.0;
            }
        for (int col = 0; col < 4; col++) {
            int p = col; double best = fabs(a[col][col]);
            for (int r = col+1; r < 4; r++) {
                double v = fabs(a[r][col]);
                if (v > best) { best = v; p = r; }
            }
            if (p != col)
                for (int c2 = 0; c2 < 8; c2++) {
                    double t = a[col][c2]; a[col][c2] = a[p][c2]; a[p][c2] = t;
                }
            double pi = 1.0 / a[col][col];
            for (int c2 = 0; c2 < 8; c2++) a[col][c2] *= pi;
            for (int r = 0; r < 4; r++) if (r != col) {
                double f = a[r][col];
                for (int c2 = 0; c2 < 8; c2++) a[r][c2] -= f*a[col][c2];
            }
        }
        for (int v = 1; v < NV; v++) {
            const float* S = proj + ((size_t)b*NV + v)*16;
            for (int r = 0; r < 3; r++) {
                double pr[4];
                for (int c2 = 0; c2 < 4; c2++) {
                    double s = 0.0;
                    for (int k = 0; k < 4; k++) s += (double)S[r*4+k]*a[k][4+c2];
                    pr[c2] = s;
                }
                g_rot[b][v-1][r*3+0] = (float)pr[0];
                g_rot[b][v-1][r*3+1] = (float)pr[1];
                g_rot[b][v-1][r*3+2] = (float)pr[2];
                g_trans[b][v-1][r]   = (float)pr[3];
            }
        }
    }
}

// ---------------- transpose (V,B,C,H,W) -> (V,B,cg,H,W,4), coalesced STG.128 --
__global__ void transpose_kernel(const float* __restrict__ feat) {
    __shared__ float t[32][33];
    int vb = blockIdx.y;
    int hw0 = blockIdx.x * 32;
    const float* src = feat + (size_t)vb*NC*NHW;
    #pragma unroll
    for (int cc = threadIdx.y; cc < 32; cc += 8)
        t[cc][threadIdx.x] = src[(size_t)cc*NHW + hw0 + threadIdx.x];
    __syncthreads();
    int tx = threadIdx.x;     // pixel within group of 32
    int cg = threadIdx.y;     // 0..7
    float4 val = make_float4(t[4*cg+0][tx], t[4*cg+1][tx], t[4*cg+2][tx], t[4*cg+3][tx]);
    float4* dst = (float4*)g_featT + (size_t)vb*8*NHW + (size_t)cg*NHW + hw0 + tx;
    *dst = val;
}

// ---------------- bilinear descriptor + gather ----------------
__device__ __forceinline__ void make_desc(float px, float py, int* off, ull* wgt) {
    float x0f = floorf(px), y0f = floorf(py);
    float wx1 = px - x0f, wy1 = py - y0f;
    float wx0 = 1.f - wx1, wy0 = 1.f - wy1;
    float x1f = x0f + 1.f, y1f = y0f + 1.f;
    float vx0 = (x0f >= 0.f && x0f <= (float)(NW-1)) ? 1.f : 0.f;
    float vx1 = (x1f >= 0.f && x1f <= (float)(NW-1)) ? 1.f : 0.f;
    float vy0 = (y0f >= 0.f && y0f <= (float)(NH-1)) ? 1.f : 0.f;
    float vy1 = (y1f >= 0.f && y1f <= (float)(NH-1)) ? 1.f : 0.f;
    int ix0 = (int)fminf(fmaxf(x0f, 0.f), (float)(NW-1));
    int ix1 = (int)fminf(fmaxf(x1f, 0.f), (float)(NW-1));
    int iy0 = (int)fminf(fmaxf(y0f, 0.f), (float)(NH-1));
    int iy1 = (int)fminf(fmaxf(y1f, 0.f), (float)(NH-1));
    off[0] = iy0*NW+ix0; off[1] = iy0*NW+ix1;
    off[2] = iy1*NW+ix0; off[3] = iy1*NW+ix1;
    wgt[0] = dup2(wx0*wy0*vx0*vy0); wgt[1] = dup2(wx1*wy0*vx1*vy0);
    wgt[2] = dup2(wx0*wy1*vx0*vy1); wgt[3] = dup2(wx1*wy1*vx1*vy1);
}

__device__ __forceinline__ void gath(const ulonglong2* __restrict__ bp,
                                     const int* off, const ull* wgt,
                                     ull& s01, ull& s23, ull& q01, ull& q23) {
    ulonglong2 f0 = __ldg(bp+off[0]), f1 = __ldg(bp+off[1]);
    ulonglong2 f2 = __ldg(bp+off[2]), f3 = __ldg(bp+off[3]);
    ull a01 = mul2(f0.x, wgt[0]); a01 = fma2(f1.x, wgt[1], a01);
    a01 = fma2(f2.x, wgt[2], a01); a01 = fma2(f3.x, wgt[3], a01);
    ull a23 = mul2(f0.y, wgt[0]); a23 = fma2(f1.y, wgt[1], a23);
    a23 = fma2(f2.y, wgt[2], a23); a23 = fma2(f3.y, wgt[3], a23);
    s01 = add2(s01, a01); q01 = fma2(a01, a01, q01);
    s23 = add2(s23, a23); q23 = fma2(a23, a23, q23);
}

// ---------------- kernel V: warp + 3-view variance -> fp16 volume -------------
__global__ __launch_bounds__(256)
void var_kernel(const float* __restrict__ dvals) {
    int gid = blockIdx.x*256 + threadIdx.x;
    int w = gid % NW; int t = gid / NW;
    int h = t & (NH-1); t >>= 7;
    int d = t % ND; int b = t / ND;
    float dep = __ldg(&dvals[b*ND + d]);
    float fx = (float)w, fy = (float)h;

    int off[2][4]; ull wgt[2][4];
    #pragma unroll
    for (int v = 0; v < 2; v++) {
        float rx = g_rot[b][v][0]*fx + g_rot[b][v][1]*fy + g_rot[b][v][2];
        float ry = g_rot[b][v][3]*fx + g_rot[b][v][4]*fy + g_rot[b][v][5];
        float rz = g_rot[b][v][6]*fx + g_rot[b][v][7]*fy + g_rot[b][v][8];
        float px = rx*dep + g_trans[b][v][0];
        float py = ry*dep + g_trans[b][v][1];
        float pz = rz*dep + g_trans[b][v][2];
        if (fabsf(pz) < 1e-6f) pz = 1e-6f;
        make_desc(px/pz, py/pz, off[v], wgt[v]);
    }

    const ulonglong2* fb = (const ulonglong2*)g_featT;
    const int ro = h*NW + w;
    const size_t outRow = (size_t)d*NHW + ro;

    #pragma unroll 2
    for (int pr = 0; pr < 4; pr++) {
        const int cgA = pr*2, cgB = cgA + 1;
        const ulonglong2* refA = fb + ((size_t)b*8 + cgA)*NHW;
        const ulonglong2* refB = refA + NHW;
        const ulonglong2* v1A  = fb + ((size_t)(NB + b)*8 + cgA)*NHW;
        const ulonglong2* v1B  = v1A + NHW;
        const ulonglong2* v2A  = fb + ((size_t)(2*NB + b)*8 + cgA)*NHW;
        const ulonglong2* v2B  = v2A + NHW;

        ulonglong2 rA = __ldg(refA + ro), rB = __ldg(refB + ro);
        ull sA01 = rA.x, sA23 = rA.y, sB01 = rB.x, sB23 = rB.y;
        ull qA01 = mul2(rA.x, rA.x), qA23 = mul2(rA.y, rA.y);
        ull qB01 = mul2(rB.x, rB.x), qB23 = mul2(rB.y, rB.y);

        gath(v1A, off[0], wgt[0], sA01, sA23, qA01, qA23);
        gath(v2A, off[1], wgt[1], sA01, sA23, qA01, qA23);
        gath(v1B, off[0], wgt[0], sB01, sB23, qB01, qB23);
        gath(v2B, off[1], wgt[1], sB01, sB23, qB01, qB23);

        ull m, x01, x23;
        uint2 oA, oB;
        m = mul2(sA01, INV3P); x01 = fma2(m ^ NEGMASK, m, mul2(qA01, INV3P));
        m = mul2(sA23, INV3P); x23 = fma2(m ^ NEGMASK, m, mul2(qA23, INV3P));
        oA.x = pkh2(x01); oA.y = pkh2(x23);
        m = mul2(sB01, INV3P); x01 = fma2(m ^ NEGMASK, m, mul2(qB01, INV3P));
        m = mul2(sB23, INV3P); x23 = fma2(m ^ NEGMASK, m, mul2(qB23, INV3P));
        oB.x = pkh2(x01); oB.y = pkh2(x23);

        g_varH[((size_t)b*8 + cgA)*ND*NHW + outRow] = oA;
        g_varH[((size_t)b*8 + cgB)*ND*NHW + outRow] = oB;
    }
}

// ---------------- kernel C: tiled 3^3 conv, hoisted load-phase geometry -------
#define CTD 4
#define CTH 16
#define CTW 32
#define NZC (ND/CTD)         // 12
#define CHD (CTD+2)          // 6
#define CHHs (CTH+2)         // 18
#define CHWs (CTW+2)         // 34
#define CPLANE (CHHs*CHWs)   // 612
#define CVOL (CHD*CPLANE)    // 3672
// smem: sV[2 chp][CVOL] f32-pairs (ull) + weights
#define CSMEM (2*CVOL*8 + 864*4)   // 62208 -> 3 blocks/SM

__global__ __launch_bounds__(256, 3)
void conv_kernel() {
    extern __shared__ unsigned char smem_raw[];
    ull*   s0 = (ull*)smem_raw;            // chp 0 plane: f32x2 per pixel
    ull*   s1 = s0 + CVOL;                 // chp 1 plane
    float* sW = (float*)(smem_raw + 2*CVOL*8);

    const int tid = threadIdx.x;
    const int b  = blockIdx.z / NZC;
    const int d0 = (blockIdx.z - b*NZC)*CTD;
    const int h0 = blockIdx.y * CTH;
    const int w0 = blockIdx.x * CTW;

    for (int i = tid; i < 864; i += 256) sW[i] = g_wcf[i];

    // ---- hoisted geometry: this thread's <=3 plane positions, cg/hd-invariant
    int goff[3]; int gok[3];
    #pragma unroll
    for (int j = 0; j < 3; j++) {
        int i = tid + 256*j;
        int ok = 0, off = 0;
        if (i < CPLANE) {
            int hh = i / CHWs, ww = i - hh*CHWs;
            int h = h0 + hh - 1, w = w0 + ww - 1;
            ok = ((unsigned)h < (unsigned)NH) && ((unsigned)w < (unsigned)NW);
            off = h*NW + w;
        }
        gok[j] = ok; goff[j] = off;
    }
    const bool has3 = (tid + 512) < CPLANE;

    const int hl = tid >> 4;        // 0..15 output row
    const int wp = (tid & 15) * 2;  // owns w = wp, wp+1

    ull acc[CTD][2];
    #pragma unroll
    for (int o = 0; o < CTD; o++) { acc[o][0] = 0; acc[o][1] = 0; }

    #pragma unroll 1
    for (int cg = 0; cg < 8; cg++) {
        // ---- load halo tile: fp16 gmem -> fp32 planar smem (convert ONCE) ----
        const uint2* gvc = g_varH + ((size_t)b*8 + cg)*ND*NHW;
        #pragma unroll
        for (int hd = 0; hd < CHD; hd++) {
            int d = d0 - 1 + hd;
            int dok = ((unsigned)d < (unsigned)ND);
            const uint2* rowp = gvc + (long)d*NHW;
            #pragma unroll
            for (int j = 0; j < 3; j++) {
                if (j < 2 || has3) {
                    uint2 v; v.x = 0; v.y = 0;
                    if (dok && gok[j]) v = __ldg(rowp + goff[j]);
                    int si = hd*CPLANE + tid + 256*j;
                    s0[si] = h2f2(v.x);
                    s1[si] = h2f2(v.y);
                }
            }
        }
        __syncthreads();

        #pragma unroll 1
        for (int chp = 0; chp < 2; chp++) {
            const ull* sVc = chp ? s1 : s0;
            const ull* wb = (const ull*)sW + (cg*2 + chp)*27;
            #pragma unroll
            for (int kh = 0; kh < 3; kh++) {
                ull wk[3][3];   // [kw][kd] packed ch-pair weights
                #pragma unroll
                for (int kw = 0; kw < 3; kw++)
                    #pragma unroll
                    for (int kd = 0; kd < 3; kd++)
                        wk[kw][kd] = wb[(kh*3 + kw)*3 + kd];
                const ull* rowb = sVc + (hl + kh)*CHWs + wp;
                #pragma unroll
                for (int hd = 0; hd < CHD; hd++) {
                    // even ull index -> 16B aligned; 2x LDS.128, 4 pixels fp32
                    ulonglong2 va = *(const ulonglong2*)(rowb + hd*CPLANE);
                    ulonglong2 vb2 = *(const ulonglong2*)(rowb + hd*CPLANE + 2);
                    ull c0 = va.x, c1 = va.y, c2 = vb2.x, c3 = vb2.y;
                    #pragma unroll
                    for (int kd = 0; kd < 3; kd++) {
                        const int o = hd - kd;
                        if (o >= 0 && o < CTD) {
                            acc[o][0] = fma2(c0, wk[0][kd], acc[o][0]);
                            acc[o][0] = fma2(c1, wk[1][kd], acc[o][0]);
                            acc[o][0] = fma2(c2, wk[2][kd], acc[o][0]);
                            acc[o][1] = fma2(c1, wk[0][kd], acc[o][1]);
                            acc[o][1] = fma2(c2, wk[1][kd], acc[o][1]);
                            acc[o][1] = fma2(c3, wk[2][kd], acc[o][1]);
                        }
                    }
                }
            }
        }
        __syncthreads();
    }

    const float bias = g_bias;
    #pragma unroll
    for (int o = 0; o < CTD; o++) {
        size_t base = (((size_t)b*ND + d0 + o)*NH + (h0 + hl))*NW + w0 + wp;
        float2 r;
        r.x = sum2(acc[o][0]) + bias;
        r.y = sum2(acc[o][1]) + bias;
        *(float2*)(g_cost + base) = r;
    }
}

// ---------------- softmax over depth + expected depth + confidence ----------------
__global__ __launch_bounds__(256)
void softmax_kernel(const float* __restrict__ dvals, float* __restrict__ out) {
    int gid = blockIdx.x*blockDim.x + threadIdx.x;
    if (gid >= NB*NHW) return;
    int b = gid / NHW;
    int hw = gid - b*NHW;
    const float* cp = g_cost + (size_t)b*ND*NHW + hw;
    float c[ND];
    float mx = -3.4e38f;
    #pragma unroll
    for (int d = 0; d < ND; d++) {
        c[d] = cp[(size_t)d*NHW];
        mx = fmaxf(mx, c[d]);
    }
    float sum = 0.f;
    #pragma unroll
    for (int d = 0; d < ND; d++) {
        c[d] = __expf(c[d] - mx);
        sum += c[d];
    }
    float inv = 1.f/sum;
    float depth = 0.f, fidx = 0.f;
    #pragma unroll
    for (int d = 0; d < ND; d++) {
        depth += c[d]*__ldg(&dvals[b*ND + d]);
        fidx  += c[d]*(float)d;
    }
    depth *= inv;
    fidx  *= inv;
    int di = (int)fidx;
    di = min(max(di, 0), ND-1);
    float conf = 0.f;
    #pragma unroll
    for (int d = 0; d < ND; d++) {
        if (d >= di-1 && d <= di+2) conf += c[d];
    }
    conf *= inv;
    out[gid] = depth;
    out[NB*NHW + gid] = conf;
}

// ---------------- launch ----------------
extern "C" void kernel_launch(void* const* d_in, const int* in_sizes, int n_in,
                              void* d_out, int out_size) {
    const float* features = (const float*)d_in[0];   // (V,B,C,H,W)
    const float* proj     = (const float*)d_in[1];   // (B,V,4,4)
    const float* dvals    = (const float*)d_in[2];   // (B,D)
    int iw = 3;
    while (iw < n_in && in_sizes[iw] != 27*NC) iw++;
    const float* rw = (const float*)d_in[iw];
    const float* rb = (const float*)d_in[iw+1];

    cudaFuncSetAttribute(conv_kernel,
                         cudaFuncAttributeMaxDynamicSharedMemorySize, CSMEM);

    prep_kernel<<<1, 256>>>(proj, rw, rb);
    transpose_kernel<<<dim3(NHW/32, NV*NB), dim3(32, 8)>>>(features);
    var_kernel<<<(NB*ND*NHW)/256, 256>>>(dvals);
    conv_kernel<<<dim3(NW/CTW, NH/CTH, NB*NZC), 256, CSMEM>>>();
    softmax_kernel<<<(NB*NHW + 255)/256, 256>>>(dvals, (float*)d_out);
}

// round 15
// speedup vs baseline: 1.1840x; 1.1840x over previous
#include <cuda_runtime.h>
#include <cuda_fp16.h>
#include <math.h>

// ---------------- problem constants ----------------
#define NB 2
#define NV 3
#define NC 32
#define ND 48
#define NH 128
#define NW 160
#define NHW (NH*NW)          // 20480

typedef unsigned long long ull;

// ---------------- device scratch ----------------
// Feature layout: (V, B, cg=8, H, W, 4ch) fp32, pixel stride 16B
__device__ __align__(128) float g_featT[(size_t)NV*NB*NHW*NC];
// Variance volume fp16: (B, cg=8, D, H, W) x 4ch packed in uint2 (2x half2)
__device__ __align__(128) uint2 g_varH[(size_t)NB*8*ND*NHW];
__device__ __align__(16) float g_cost[(size_t)NB*ND*NHW];
__device__ float g_rot[NB][2][9];
__device__ float g_trans[NB][2][3];
// conv weights as float2 per (cg,chp,kh,kw,kd): [(cg*2+chp)*27 + (kh*3+kw)*3 + kd]
__device__ __align__(16) float g_wcf[864];
__device__ float g_bias;

// ---------------- packed f32x2 helpers ----------------
__device__ __forceinline__ ull fma2(ull a, ull b, ull c) {
    ull d; asm("fma.rn.f32x2 %0, %1, %2, %3;" : "=l"(d) : "l"(a), "l"(b), "l"(c)); return d;
}
__device__ __forceinline__ ull mul2(ull a, ull b) {
    ull d; asm("mul.rn.f32x2 %0, %1, %2;" : "=l"(d) : "l"(a), "l"(b)); return d;
}
__device__ __forceinline__ ull add2(ull a, ull b) {
    ull d; asm("add.rn.f32x2 %0, %1, %2;" : "=l"(d) : "l"(a), "l"(b)); return d;
}
__device__ __forceinline__ ull dup2(float f) {
    ull d; int r = __float_as_int(f);
    asm("mov.b64 %0, {%1, %1};" : "=l"(d) : "r"(r)); return d;
}
__device__ __forceinline__ float sum2(ull v) {
    int lo, hi; asm("mov.b64 {%0, %1}, %2;" : "=r"(lo), "=r"(hi) : "l"(v));
    return __int_as_float(lo) + __int_as_float(hi);
}
// f32x2 (ull) -> half2 bits
__device__ __forceinline__ unsigned pkh2(ull v) {
    float lo, hi;
    asm("mov.b64 {%0, %1}, %2;" : "=f"(lo), "=f"(hi) : "l"(v));
    unsigned r;
    asm("cvt.rn.f16x2.f32 %0, %1, %2;" : "=r"(r) : "f"(hi), "f"(lo));
    return r;
}
// half2 bits -> f32x2 (ull)
__device__ __forceinline__ ull h2f2(unsigned h) {
    float lo, hi;
    asm("{ .reg .f16 l, u; mov.b32 {l, u}, %2; cvt.f32.f16 %0, l; cvt.f32.f16 %1, u; }"
        : "=f"(lo), "=f"(hi) : "r"(h));
    ull d; asm("mov.b64 %0, {%1, %2};" : "=l"(d) : "f"(lo), "f"(hi));
    return d;
}
#define NEGMASK 0x8000000080000000ULL
#define INV3P   0x3eaaaaab3eaaaaabULL   // (1/3, 1/3)

// ---------------- prep: proj @ inv(ref_proj), weight relayout ----------------
__global__ void prep_kernel(const float* __restrict__ proj,
                            const float* __restrict__ rw,
                            const float* __restrict__ rb) {
    int tid = threadIdx.x;
    // rw layout (1,C,3,3,3): rw[c*27 + kd*9 + kh*3 + kw], c = cg*4 + chp*2 + lane
    for (int i = tid; i < 27*NC; i += blockDim.x) {
        int c = i / 27, k = i - c*27;
        int kd = k / 9, kh = (k - kd*9) / 3, kw = k % 3;
        int cg = c >> 2, chp = (c >> 1) & 1, lane = c & 1;
        g_wcf[(((cg*2 + chp)*27) + (kh*3 + kw)*3 + kd)*2 + lane] = rw[i];
    }
    if (tid == 0) g_bias = rb[0];
    if (tid < NB) {
        int b = tid;
        const float* refp = proj + ((size_t)b*NV + 0)*16;
        double a[4][8];
        for (int r = 0; r < 4; r++)
            for (int c2 = 0; c2 < 4; c2++) {
                a[r][c2] = (double)refp[r*4+c2];
                a[r][4+c2] = (r == c2) ? 1.0 : 0.0;
            }
        for (int col = 0; col < 4; col++) {
            int p = col; double best = fabs(a[col][col]);
            for (int r = col+1; r < 4; r++) {
                double v = fabs(a[r][col]);
                if (v > best) { best = v; p = r; }
            }
            if (p != col)
                for (int c2 = 0; c2 < 8; c2++) {
                    double t = a[col][c2]; a[col][c2] = a[p][c2]; a[p][c2] = t;
                }
            double pi = 1.0 / a[col][col];
            for (int c2 = 0; c2 < 8; c2++) a[col][c2] *= pi;
            for (int r = 0; r < 4; r++) if (r != col) {
                double f = a[r][col];
                for (int c2 = 0; c2 < 8; c2++) a[r][c2] -= f*a[col][c2];
            }
        }
        for (int v = 1; v < NV; v++) {
            const float* S = proj + ((size_t)b*NV + v)*16;
            for (int r = 0; r < 3; r++) {
                double pr[4];
                for (int c2 = 0; c2 < 4; c2++) {
                    double s = 0.0;
                    for (int k = 0; k < 4; k++) s += (double)S[r*4+k]*a[k][4+c2];
                    pr[c2] = s;
                }
                g_rot[b][v-1][r*3+0] = (float)pr[0];
                g_rot[b][v-1][r*3+1] = (float)pr[1];
                g_rot[b][v-1][r*3+2] = (float)pr[2];
                g_trans[b][v-1][r]   = (float)pr[3];
            }
        }
    }
}

// ---------------- transpose (V,B,C,H,W) -> (V,B,cg,H,W,4), coalesced STG.128 --
__global__ void transpose_kernel(const float* __restrict__ feat) {
    __shared__ float t[32][33];
    int vb = blockIdx.y;
    int hw0 = blockIdx.x * 32;
    const float* src = feat + (size_t)vb*NC*NHW;
    #pragma unroll
    for (int cc = threadIdx.y; cc < 32; cc += 8)
        t[cc][threadIdx.x] = src[(size_t)cc*NHW + hw0 + threadIdx.x];
    __syncthreads();
    int tx = threadIdx.x;     // pixel within group of 32
    int cg = threadIdx.y;     // 0..7
    float4 val = make_float4(t[4*cg+0][tx], t[4*cg+1][tx], t[4*cg+2][tx], t[4*cg+3][tx]);
    float4* dst = (float4*)g_featT + (size_t)vb*8*NHW + (size_t)cg*NHW + hw0 + tx;
    *dst = val;
}

// ---------------- kernel V: depth-marching variance with register tap cache ---
// Thread = (b, cg, h, w); marches d=0..ND-1. Bilinear integer cell changes
// rarely across depth (sub-pixel parallax per step), so the 4 feature taps per
// view are cached in registers keyed on (floor(px), floor(py)) and reloaded
// only on key change. Exact math regardless of geometry.
__global__ __launch_bounds__(256)
void var_kernel(const float* __restrict__ dvals) {
    int gid = blockIdx.x*256 + threadIdx.x;
    int w = gid % NW; int t = gid / NW;
    int h = t % NH; t /= NH;
    int cg = t & 7; int b = t >> 3;

    const ulonglong2* fb = (const ulonglong2*)g_featT;
    const ulonglong2* refp = fb + ((size_t)b*8 + cg)*NHW;
    const ulonglong2* v1p  = fb + ((size_t)(NB + b)*8 + cg)*NHW;
    const ulonglong2* v2p  = fb + ((size_t)(2*NB + b)*8 + cg)*NHW;

    const int ro = h*NW + w;
    const ulonglong2 r = __ldg(refp + ro);
    const ull rq01 = mul2(r.x, r.x), rq23 = mul2(r.y, r.y);

    float fx = (float)w, fy = (float)h;
    float rx[2], ry[2], rz[2], t0[2], t1[2], t2[2];
    #pragma unroll
    for (int v = 0; v < 2; v++) {
        rx[v] = g_rot[b][v][0]*fx + g_rot[b][v][1]*fy + g_rot[b][v][2];
        ry[v] = g_rot[b][v][3]*fx + g_rot[b][v][4]*fy + g_rot[b][v][5];
        rz[v] = g_rot[b][v][6]*fx + g_rot[b][v][7]*fy + g_rot[b][v][8];
        t0[v] = g_trans[b][v][0];
        t1[v] = g_trans[b][v][1];
        t2[v] = g_trans[b][v][2];
    }

    float cx[2] = {1e30f, 1e30f}, cy[2] = {1e30f, 1e30f};
    ulonglong2 tp[2][4];
    #pragma unroll
    for (int v = 0; v < 2; v++)
        #pragma unroll
        for (int k = 0; k < 4; k++) { tp[v][k].x = 0; tp[v][k].y = 0; }

    uint2* outp = g_varH + ((size_t)b*8 + cg)*ND*NHW + ro;
    const float* dv = dvals + b*ND;

    #pragma unroll 1
    for (int d = 0; d < ND; d++) {
        float dep = __ldg(dv + d);
        ull s01 = r.x, s23 = r.y, q01 = rq01, q23 = rq23;
        #pragma unroll
        for (int v = 0; v < 2; v++) {
            float pz = rz[v]*dep + t2[v];
            if (fabsf(pz) < 1e-6f) pz = 1e-6f;
            float px = __fdividef(rx[v]*dep + t0[v], pz);
            float py = __fdividef(ry[v]*dep + t1[v], pz);
            float x0f = floorf(px), y0f = floorf(py);
            if (x0f != cx[v] || y0f != cy[v]) {
                cx[v] = x0f; cy[v] = y0f;
                int ix0 = (int)fminf(fmaxf(x0f,       0.f), (float)(NW-1));
                int ix1 = (int)fminf(fmaxf(x0f + 1.f, 0.f), (float)(NW-1));
                int iy0 = (int)fminf(fmaxf(y0f,       0.f), (float)(NH-1));
                int iy1 = (int)fminf(fmaxf(y0f + 1.f, 0.f), (float)(NH-1));
                const ulonglong2* bp = v ? v2p : v1p;
                tp[v][0] = __ldg(bp + (iy0*NW + ix0));
                tp[v][1] = __ldg(bp + (iy0*NW + ix1));
                tp[v][2] = __ldg(bp + (iy1*NW + ix0));
                tp[v][3] = __ldg(bp + (iy1*NW + ix1));
            }
            float wx1 = px - x0f, wy1 = py - y0f;
            float wx0 = 1.f - wx1, wy0 = 1.f - wy1;
            float vx0 = (x0f >= 0.f && x0f <= (float)(NW-1)) ? 1.f : 0.f;
            float vx1 = (x0f + 1.f >= 0.f && x0f + 1.f <= (float)(NW-1)) ? 1.f : 0.f;
            float vy0 = (y0f >= 0.f && y0f <= (float)(NH-1)) ? 1.f : 0.f;
            float vy1 = (y0f + 1.f >= 0.f && y0f + 1.f <= (float)(NH-1)) ? 1.f : 0.f;
            ull W00 = dup2(wx0*wy0*vx0*vy0);
            ull W01 = dup2(wx1*wy0*vx1*vy0);
            ull W10 = dup2(wx0*wy1*vx0*vy1);
            ull W11 = dup2(wx1*wy1*vx1*vy1);
            ull a01 = mul2(tp[v][0].x, W00); a01 = fma2(tp[v][1].x, W01, a01);
            a01 = fma2(tp[v][2].x, W10, a01); a01 = fma2(tp[v][3].x, W11, a01);
            ull a23 = mul2(tp[v][0].y, W00); a23 = fma2(tp[v][1].y, W01, a23);
            a23 = fma2(tp[v][2].y, W10, a23); a23 = fma2(tp[v][3].y, W11, a23);
            s01 = add2(s01, a01); q01 = fma2(a01, a01, q01);
            s23 = add2(s23, a23); q23 = fma2(a23, a23, q23);
        }
        ull m;
        m = mul2(s01, INV3P); ull x01 = fma2(m ^ NEGMASK, m, mul2(q01, INV3P));
        m = mul2(s23, INV3P); ull x23 = fma2(m ^ NEGMASK, m, mul2(q23, INV3P));
        uint2 o; o.x = pkh2(x01); o.y = pkh2(x23);
        outp[(size_t)d*NHW] = o;
    }
}

// ---------------- kernel C: tiled 3^3 conv, fp32-planar smem (R12 config) -----
#define CTD 4
#define CTH 16
#define CTW 32
#define NZC (ND/CTD)         // 12
#define CHD (CTD+2)          // 6
#define CHHs (CTH+2)         // 18
#define CHWs (CTW+2)         // 34
#define CPLANE (CHHs*CHWs)   // 612
#define CVOL (CHD*CPLANE)    // 3672
// smem: sV[2 chp][CVOL] f32-pairs (ull) + weights
#define CSMEM (2*CVOL*8 + 864*4)   // 62208 -> 3 blocks/SM

__global__ __launch_bounds__(256, 3)
void conv_kernel() {
    extern __shared__ unsigned char smem_raw[];
    ull*   s0 = (ull*)smem_raw;            // chp 0 plane: f32x2 per pixel
    ull*   s1 = s0 + CVOL;                 // chp 1 plane
    float* sW = (float*)(smem_raw + 2*CVOL*8);

    const int tid = threadIdx.x;
    const int b  = blockIdx.z / NZC;
    const int d0 = (blockIdx.z - b*NZC)*CTD;
    const int h0 = blockIdx.y * CTH;
    const int w0 = blockIdx.x * CTW;

    for (int i = tid; i < 864; i += 256) sW[i] = g_wcf[i];

    const int hl = tid >> 4;        // 0..15 output row
    const int wp = (tid & 15) * 2;  // owns w = wp, wp+1

    ull acc[CTD][2];
    #pragma unroll
    for (int o = 0; o < CTD; o++) { acc[o][0] = 0; acc[o][1] = 0; }

    #pragma unroll 1
    for (int cg = 0; cg < 8; cg++) {
        // ---- load halo tile: fp16 gmem -> fp32 planar smem (convert ONCE) ----
        const uint2* gvc = g_varH + ((size_t)b*8 + cg)*ND*NHW;
        for (int i = tid; i < CVOL; i += 256) {
            int hd = i / CPLANE;
            int p  = i - hd*CPLANE;
            int hh = p / CHWs;
            int ww = p - hh*CHWs;
            int d = d0 - 1 + hd, h = h0 + hh - 1, w = w0 + ww - 1;
            uint2 v; v.x = 0; v.y = 0;
            if ((unsigned)d < (unsigned)ND && (unsigned)h < (unsigned)NH &&
                (unsigned)w < (unsigned)NW)
                v = __ldg(gvc + (size_t)d*NHW + h*NW + w);
            s0[i] = h2f2(v.x);
            s1[i] = h2f2(v.y);
        }
        __syncthreads();

        #pragma unroll 1
        for (int chp = 0; chp < 2; chp++) {
            const ull* sVc = chp ? s1 : s0;
            const ull* wb = (const ull*)sW + (cg*2 + chp)*27;
            #pragma unroll
            for (int kh = 0; kh < 3; kh++) {
                ull wk[3][3];   // [kw][kd] packed ch-pair weights
                #pragma unroll
                for (int kw = 0; kw < 3; kw++)
                    #pragma unroll
                    for (int kd = 0; kd < 3; kd++)
                        wk[kw][kd] = wb[(kh*3 + kw)*3 + kd];
                const ull* rowb = sVc + (hl + kh)*CHWs + wp;
                #pragma unroll
                for (int hd = 0; hd < CHD; hd++) {
                    // even ull index -> 16B aligned; 2x LDS.128, 4 pixels fp32
                    ulonglong2 va = *(const ulonglong2*)(rowb + hd*CPLANE);
                    ulonglong2 vb2 = *(const ulonglong2*)(rowb + hd*CPLANE + 2);
                    ull c0 = va.x, c1 = va.y, c2 = vb2.x, c3 = vb2.y;
                    #pragma unroll
                    for (int kd = 0; kd < 3; kd++) {
                        const int o = hd - kd;
                        if (o >= 0 && o < CTD) {
                            acc[o][0] = fma2(c0, wk[0][kd], acc[o][0]);
                            acc[o][0] = fma2(c1, wk[1][kd], acc[o][0]);
                            acc[o][0] = fma2(c2, wk[2][kd], acc[o][0]);
                            acc[o][1] = fma2(c1, wk[0][kd], acc[o][1]);
                            acc[o][1] = fma2(c2, wk[1][kd], acc[o][1]);
                            acc[o][1] = fma2(c3, wk[2][kd], acc[o][1]);
                        }
                    }
                }
            }
        }
        __syncthreads();
    }

    const float bias = g_bias;
    #pragma unroll
    for (int o = 0; o < CTD; o++) {
        size_t base = (((size_t)b*ND + d0 + o)*NH + (h0 + hl))*NW + w0 + wp;
        float2 r;
        r.x = sum2(acc[o][0]) + bias;
        r.y = sum2(acc[o][1]) + bias;
        *(float2*)(g_cost + base) = r;
    }
}

// ---------------- softmax over depth + expected depth + confidence ----------------
__global__ __launch_bounds__(256)
void softmax_kernel(const float* __restrict__ dvals, float* __restrict__ out) {
    int gid = blockIdx.x*blockDim.x + threadIdx.x;
    if (gid >= NB*NHW) return;
    int b = gid / NHW;
    int hw = gid - b*NHW;
    const float* cp = g_cost + (size_t)b*ND*NHW + hw;
    float c[ND];
    float mx = -3.4e38f;
    #pragma unroll
    for (int d = 0; d < ND; d++) {
        c[d] = cp[(size_t)d*NHW];
        mx = fmaxf(mx, c[d]);
    }
    float sum = 0.f;
    #pragma unroll
    for (int d = 0; d < ND; d++) {
        c[d] = __expf(c[d] - mx);
        sum += c[d];
    }
    float inv = 1.f/sum;
    float depth = 0.f, fidx = 0.f;
    #pragma unroll
    for (int d = 0; d < ND; d++) {
        depth += c[d]*__ldg(&dvals[b*ND + d]);
        fidx  += c[d]*(float)d;
    }
    depth *= inv;
    fidx  *= inv;
    int di = (int)fidx;
    di = min(max(di, 0), ND-1);
    float conf = 0.f;
    #pragma unroll
    for (int d = 0; d < ND; d++) {
        if (d >= di-1 && d <= di+2) conf += c[d];
    }
    conf *= inv;
    out[gid] = depth;
    out[NB*NHW + gid] = conf;
}

// ---------------- launch ----------------
extern "C" void kernel_launch(void* const* d_in, const int* in_sizes, int n_in,
                              void* d_out, int out_size) {
    const float* features = (const float*)d_in[0];   // (V,B,C,H,W)
    const float* proj     = (const float*)d_in[1];   // (B,V,4,4)
    const float* dvals    = (const float*)d_in[2];   // (B,D)
    int iw = 3;
    while (iw < n_in && in_sizes[iw] != 27*NC) iw++;
    const float* rw = (const float*)d_in[iw];
    const float* rb = (const float*)d_in[iw+1];

    cudaFuncSetAttribute(conv_kernel,
                         cudaFuncAttributeMaxDynamicSharedMemorySize, CSMEM);

    prep_kernel<<<1, 256>>>(proj, rw, rb);
    transpose_kernel<<<dim3(NHW/32, NV*NB), dim3(32, 8)>>>(features);
    var_kernel<<<(NB*8*NHW)/256, 256>>>(dvals);
    conv_kernel<<<dim3(NW/CTW, NH/CTH, NB*NZC), 256, CSMEM>>>();
    softmax_kernel<<<(NB*NHW + 255)/256, 256>>>(dvals, (float*)d_out);
}